// round 5
// baseline (speedup 1.0000x reference)
#include <cuda_runtime.h>
#include <math.h>

#define NB   8
#define C    256
#define H    112
#define W    112
#define L    224              // H + W
#define PLANES (NB * C)       // 2048
#define TOTAL4 (NB * C * H * W / 4)   // 6,422,528 float4

// scratch: pooled means [n][c][pos] (pos<112: W-mean per row h, else H-mean per col w)
__device__ __align__(16) float g_pool[NB * C * L];
__device__ __align__(16) float g_att [NB * C * L];

// ---------------------------------------------------------------------------
// Kernel 1: one block (256 thr, 8 warps) per (n,c) plane. Warp w owns rows
// [14w, 14w+14). Load loop is shuffle-free straight-line code: 14 independent
// float4 loads, register column accumulation, one STS per row of the lane's
// row-partial. Final reductions done once from smem after a single sync.
// ---------------------------------------------------------------------------
__global__ void pool_kernel(const float* __restrict__ x) {
    const int plane = blockIdx.x;                 // n*C + c
    const float4* src = (const float4*)(x + (size_t)plane * (H * W));
    float* outp = g_pool + (size_t)plane * L;

    const int tid  = threadIdx.x;
    const int warp = tid >> 5, lane = tid & 31;

    __shared__ float srow[112 * 29];   // [row][lane-chunk], pad 29: conflict-free both phases
    __shared__ float scol[8][112];     // per-warp column partials

    const bool act = (lane < 28);
    const int base = warp * 14;

    float c0 = 0.f, c1 = 0.f, c2 = 0.f, c3 = 0.f;
    #pragma unroll
    for (int r = 0; r < 14; ++r) {
        float4 v = act ? __ldg(&src[(base + r) * 28 + lane])
                       : make_float4(0.f, 0.f, 0.f, 0.f);
        srow[(base + r) * 29 + lane] = (v.x + v.y) + (v.z + v.w);
        c0 += v.x; c1 += v.y; c2 += v.z; c3 += v.w;
    }
    if (act) {
        scol[warp][lane * 4 + 0] = c0;
        scol[warp][lane * 4 + 1] = c1;
        scol[warp][lane * 4 + 2] = c2;
        scol[warp][lane * 4 + 3] = c3;
    }
    __syncthreads();

    if (tid < 112) {
        // row mean over W
        const float* r = &srow[tid * 29];
        float s = 0.f;
        #pragma unroll
        for (int i = 0; i < 28; ++i) s += r[i];
        outp[tid] = s * (1.f / (float)W);
        // column mean over H
        float t = 0.f;
        #pragma unroll
        for (int w8 = 0; w8 < 8; ++w8) t += scol[w8][tid];
        outp[112 + tid] = t * (1.f / (float)H);
    }
}

// ---------------------------------------------------------------------------
// Kernel 2: per-(n,pos) block (1792 blocks, 256 threads): BN -> ds (C->8) ->
// ReLU -> us (8->C) -> sigmoid. Writes attention g_att[n][c][pos].
// ---------------------------------------------------------------------------
__global__ void att_kernel(const float* __restrict__ g1, const float* __restrict__ b1,
                           const float* __restrict__ m1, const float* __restrict__ v1,
                           const float* __restrict__ g2, const float* __restrict__ b2,
                           const float* __restrict__ m2, const float* __restrict__ v2,
                           const float* __restrict__ dsw, const float* __restrict__ dsb,
                           const float* __restrict__ usw, const float* __restrict__ usb) {
    const int b   = blockIdx.x;        // n*L + pos
    const int n   = b / L;
    const int pos = b % L;
    const int c   = threadIdx.x;       // 256

    float val = g_pool[((size_t)n * C + c) * L + pos];

    float sc, tb;
    if (pos < H) {
        float s = g1[c] * rsqrtf(v1[c] + 1e-5f);
        sc = s; tb = b1[c] - m1[c] * s;
    } else {
        float s = g2[c] * rsqrtf(v2[c] + 1e-5f);
        sc = s; tb = b2[c] - m2[c] * s;
    }
    val = fmaf(val, sc, tb);

    // down-projection partials: p[m] = dsw[m][c] * val
    float p[8];
    #pragma unroll
    for (int m = 0; m < 8; ++m) p[m] = dsw[m * C + c] * val;

    #pragma unroll
    for (int off = 16; off; off >>= 1) {
        #pragma unroll
        for (int m = 0; m < 8; ++m)
            p[m] += __shfl_down_sync(0xffffffffu, p[m], off);
    }

    __shared__ float wp[8][8];   // [warp][m]
    __shared__ float dv[8];
    const int warp = c >> 5, lane = c & 31;
    if (lane == 0) {
        #pragma unroll
        for (int m = 0; m < 8; ++m) wp[warp][m] = p[m];
    }
    __syncthreads();
    if (c < 8) {
        float s = dsb[c];
        #pragma unroll
        for (int w8 = 0; w8 < 8; ++w8) s += wp[w8][c];
        dv[c] = fmaxf(s, 0.f);       // ReLU
    }
    __syncthreads();

    float u = usb[c];
    #pragma unroll
    for (int m = 0; m < 8; ++m) u = fmaf(usw[c * 8 + m], dv[m], u);

    float a = 1.f / (1.f + expf(-u));  // sigmoid
    g_att[((size_t)n * C + c) * L + pos] = a;
}

// ---------------------------------------------------------------------------
// Kernel 3: out = hswish(x * a_w * a_h + x). 4 float4/thread at segmented
// offsets (coalescing preserved); streaming stores keep x resident in L2.
// ---------------------------------------------------------------------------
__device__ __forceinline__ float hsw(float v, float aw, float ah) {
    float t = fmaf(v * aw, ah, v);                       // v*aw*ah + v
    return t * __saturatef((t + 3.f) * (1.f / 6.f));     // t * clip(t+3,0,6)/6
}

__device__ __forceinline__ void apply_one(const float4* __restrict__ x,
                                          float4* __restrict__ out, int idx) {
    const int w4    = idx % 28;
    const int rest  = idx / 28;
    const int h     = rest % H;
    const int plane = rest / H;                                 // n*C + c

    const float  ah = __ldg(&g_att[(size_t)plane * L + h]);
    const float4 aw = __ldg((const float4*)&g_att[(size_t)plane * L + H + w4 * 4]);
    float4 v = __ldg(&x[idx]);

    float4 r;
    r.x = hsw(v.x, aw.x, ah);
    r.y = hsw(v.y, aw.y, ah);
    r.z = hsw(v.z, aw.z, ah);
    r.w = hsw(v.w, aw.w, ah);
    __stcs(&out[idx], r);      // streaming store: don't evict x from L2
}

__global__ void apply_kernel(const float4* __restrict__ x, float4* __restrict__ out) {
    const int t = blockIdx.x * blockDim.x + threadIdx.x;
    #pragma unroll
    for (int k = 0; k < 4; ++k)
        apply_one(x, out, t + k * (TOTAL4 / 4));
}

// ---------------------------------------------------------------------------
extern "C" void kernel_launch(void* const* d_in, const int* in_sizes, int n_in,
                              void* d_out, int out_size) {
    const float* x   = (const float*)d_in[0];
    const float* g1  = (const float*)d_in[1];
    const float* b1  = (const float*)d_in[2];
    const float* m1  = (const float*)d_in[3];
    const float* v1  = (const float*)d_in[4];
    const float* g2  = (const float*)d_in[5];
    const float* b2  = (const float*)d_in[6];
    const float* m2  = (const float*)d_in[7];
    const float* v2  = (const float*)d_in[8];
    const float* dsw = (const float*)d_in[9];
    const float* dsb = (const float*)d_in[10];
    const float* usw = (const float*)d_in[11];
    const float* usb = (const float*)d_in[12];
    float* out = (float*)d_out;

    pool_kernel<<<PLANES, 256>>>(x);
    att_kernel<<<NB * L, C>>>(g1, b1, m1, v1, g2, b2, m2, v2, dsw, dsb, usw, usb);
    apply_kernel<<<TOTAL4 / 4 / 256, 256>>>((const float4*)x, (float4*)out);
}

// round 6
// speedup vs baseline: 1.0156x; 1.0156x over previous
#include <cuda_runtime.h>
#include <math.h>

#define NB   8
#define C    256
#define H    112
#define W    112
#define L    224              // H + W
#define PLANES (NB * C)       // 2048
#define TOTAL4 (NB * C * H * W / 4)   // 6,422,528 float4

// scratch: pooled means [n][c][pos] (pos<112: W-mean per row h, else H-mean per col w)
__device__ __align__(16) float g_pool[NB * C * L];
__device__ __align__(16) float g_att [NB * C * L];

// ---------------------------------------------------------------------------
// Kernel 1: one block (256 thr, 8 warps) per (n,c) plane. Warp w owns rows
// [14w, 14w+14), processed as 2 halves of 7 rows. Each half front-stages 7
// independent float4 loads (MLP=7), then does 7 overlapped shuffle-tree row
// reductions (accurate) while accumulating column partials in registers.
// ---------------------------------------------------------------------------
__global__ void __launch_bounds__(256, 4) pool_kernel(const float* __restrict__ x) {
    const int plane = blockIdx.x;                 // n*C + c
    const float4* src = (const float4*)(x + (size_t)plane * (H * W));
    float* outp = g_pool + (size_t)plane * L;

    const int tid  = threadIdx.x;
    const int warp = tid >> 5, lane = tid & 31;
    __shared__ float scol[8][112];

    const bool act = (lane < 28);
    const int base = warp * 14;

    float c0 = 0.f, c1 = 0.f, c2 = 0.f, c3 = 0.f;

    #pragma unroll
    for (int half = 0; half < 2; ++half) {
        float4 v[7];
        #pragma unroll
        for (int r = 0; r < 7; ++r)
            v[r] = act ? __ldg(&src[(base + half * 7 + r) * 28 + lane])
                       : make_float4(0.f, 0.f, 0.f, 0.f);
        float rs[7];
        #pragma unroll
        for (int r = 0; r < 7; ++r)
            rs[r] = (v[r].x + v[r].y) + (v[r].z + v[r].w);
        #pragma unroll
        for (int off = 16; off; off >>= 1) {
            #pragma unroll
            for (int r = 0; r < 7; ++r)
                rs[r] += __shfl_down_sync(0xffffffffu, rs[r], off);
        }
        if (lane == 0) {
            #pragma unroll
            for (int r = 0; r < 7; ++r)
                outp[base + half * 7 + r] = rs[r] * (1.f / (float)W);
        }
        #pragma unroll
        for (int r = 0; r < 7; ++r) {
            c0 += v[r].x; c1 += v[r].y; c2 += v[r].z; c3 += v[r].w;
        }
    }

    if (act) {
        scol[warp][lane * 4 + 0] = c0;
        scol[warp][lane * 4 + 1] = c1;
        scol[warp][lane * 4 + 2] = c2;
        scol[warp][lane * 4 + 3] = c3;
    }
    __syncthreads();
    if (tid < 112) {
        float t = 0.f;
        #pragma unroll
        for (int w8 = 0; w8 < 8; ++w8) t += scol[w8][tid];
        outp[112 + tid] = t * (1.f / (float)H);
    }
}

// ---------------------------------------------------------------------------
// Kernel 2: per-(n,pos) block (1792 blocks, 256 threads): BN -> ds (C->8) ->
// ReLU -> us (8->C) -> sigmoid. Writes attention g_att[n][c][pos].
// ---------------------------------------------------------------------------
__global__ void att_kernel(const float* __restrict__ g1, const float* __restrict__ b1,
                           const float* __restrict__ m1, const float* __restrict__ v1,
                           const float* __restrict__ g2, const float* __restrict__ b2,
                           const float* __restrict__ m2, const float* __restrict__ v2,
                           const float* __restrict__ dsw, const float* __restrict__ dsb,
                           const float* __restrict__ usw, const float* __restrict__ usb) {
    const int b   = blockIdx.x;        // n*L + pos
    const int n   = b / L;
    const int pos = b % L;
    const int c   = threadIdx.x;       // 256

    float val = g_pool[((size_t)n * C + c) * L + pos];

    float sc, tb;
    if (pos < H) {
        float s = g1[c] * rsqrtf(v1[c] + 1e-5f);
        sc = s; tb = b1[c] - m1[c] * s;
    } else {
        float s = g2[c] * rsqrtf(v2[c] + 1e-5f);
        sc = s; tb = b2[c] - m2[c] * s;
    }
    val = fmaf(val, sc, tb);

    // down-projection partials: p[m] = dsw[m][c] * val
    float p[8];
    #pragma unroll
    for (int m = 0; m < 8; ++m) p[m] = dsw[m * C + c] * val;

    #pragma unroll
    for (int off = 16; off; off >>= 1) {
        #pragma unroll
        for (int m = 0; m < 8; ++m)
            p[m] += __shfl_down_sync(0xffffffffu, p[m], off);
    }

    __shared__ float wp[8][8];   // [warp][m]
    __shared__ float dv[8];
    const int warp = c >> 5, lane = c & 31;
    if (lane == 0) {
        #pragma unroll
        for (int m = 0; m < 8; ++m) wp[warp][m] = p[m];
    }
    __syncthreads();
    if (c < 8) {
        float s = dsb[c];
        #pragma unroll
        for (int w8 = 0; w8 < 8; ++w8) s += wp[w8][c];
        dv[c] = fmaxf(s, 0.f);       // ReLU
    }
    __syncthreads();

    float u = usb[c];
    #pragma unroll
    for (int m = 0; m < 8; ++m) u = fmaf(usw[c * 8 + m], dv[m], u);

    float a = 1.f / (1.f + expf(-u));  // sigmoid
    g_att[((size_t)n * C + c) * L + pos] = a;
}

// ---------------------------------------------------------------------------
// Kernel 3: out = hswish(x * a_w * a_h + x). 4 float4/thread at segmented
// offsets. Write-through stores: output never allocates in L2, so x stays
// L2-resident for this kernel's reads AND the next replay's pool reads.
// ---------------------------------------------------------------------------
__device__ __forceinline__ float hsw(float v, float aw, float ah) {
    float t = fmaf(v * aw, ah, v);                       // v*aw*ah + v
    return t * __saturatef((t + 3.f) * (1.f / 6.f));     // t * clip(t+3,0,6)/6
}

__device__ __forceinline__ void apply_one(const float4* __restrict__ x,
                                          float4* __restrict__ out, int idx) {
    const int w4    = idx % 28;
    const int rest  = idx / 28;
    const int h     = rest % H;
    const int plane = rest / H;                                 // n*C + c

    const float  ah = __ldg(&g_att[(size_t)plane * L + h]);
    const float4 aw = __ldg((const float4*)&g_att[(size_t)plane * L + H + w4 * 4]);
    float4 v = __ldg(&x[idx]);

    float4 r;
    r.x = hsw(v.x, aw.x, ah);
    r.y = hsw(v.y, aw.y, ah);
    r.z = hsw(v.z, aw.z, ah);
    r.w = hsw(v.w, aw.w, ah);
    __stwt(&out[idx], r);      // write-through: don't pollute L2
}

__global__ void apply_kernel(const float4* __restrict__ x, float4* __restrict__ out) {
    const int t = blockIdx.x * blockDim.x + threadIdx.x;
    #pragma unroll
    for (int k = 0; k < 4; ++k)
        apply_one(x, out, t + k * (TOTAL4 / 4));
}

// ---------------------------------------------------------------------------
extern "C" void kernel_launch(void* const* d_in, const int* in_sizes, int n_in,
                              void* d_out, int out_size) {
    const float* x   = (const float*)d_in[0];
    const float* g1  = (const float*)d_in[1];
    const float* b1  = (const float*)d_in[2];
    const float* m1  = (const float*)d_in[3];
    const float* v1  = (const float*)d_in[4];
    const float* g2  = (const float*)d_in[5];
    const float* b2  = (const float*)d_in[6];
    const float* m2  = (const float*)d_in[7];
    const float* v2  = (const float*)d_in[8];
    const float* dsw = (const float*)d_in[9];
    const float* dsb = (const float*)d_in[10];
    const float* usw = (const float*)d_in[11];
    const float* usb = (const float*)d_in[12];
    float* out = (float*)d_out;

    pool_kernel<<<PLANES, 256>>>(x);
    att_kernel<<<NB * L, C>>>(g1, b1, m1, v1, g2, b2, m2, v2, dsw, dsb, usw, usb);
    apply_kernel<<<TOTAL4 / 4 / 256, 256>>>((const float4*)x, (float4*)out);
}

// round 7
// speedup vs baseline: 1.0735x; 1.0570x over previous
#include <cuda_runtime.h>
#include <math.h>

#define NB   8
#define C    256
#define H    112
#define W    112
#define L    224              // H + W
#define PLANES (NB * C)       // 2048
#define TOTAL4 (NB * C * H * W / 4)   // 6,422,528 float4

// scratch: pooled means [n][c][pos] (pos<112: W-mean per row h, else H-mean per col w)
__device__ __align__(16) float g_pool[NB * C * L];
__device__ __align__(16) float g_att [NB * C * L];

// ---------------------------------------------------------------------------
// Kernel 1: one block (256 thr, 8 warps) per (n,c) plane. Warp w owns rows
// [14w, 14w+14), processed as 2 halves of 7 rows. Each half front-stages 7
// independent float4 loads (MLP=7), then 7 overlapped shuffle-tree row
// reductions; column partials in registers, combined via smem.
// ---------------------------------------------------------------------------
__global__ void __launch_bounds__(256, 4) pool_kernel(const float* __restrict__ x) {
    const int plane = blockIdx.x;                 // n*C + c
    const float4* src = (const float4*)(x + (size_t)plane * (H * W));
    float* outp = g_pool + (size_t)plane * L;

    const int tid  = threadIdx.x;
    const int warp = tid >> 5, lane = tid & 31;
    __shared__ float scol[8][112];

    const bool act = (lane < 28);
    const int base = warp * 14;

    float c0 = 0.f, c1 = 0.f, c2 = 0.f, c3 = 0.f;

    #pragma unroll
    for (int half = 0; half < 2; ++half) {
        float4 v[7];
        #pragma unroll
        for (int r = 0; r < 7; ++r)
            v[r] = act ? __ldg(&src[(base + half * 7 + r) * 28 + lane])
                       : make_float4(0.f, 0.f, 0.f, 0.f);
        float rs[7];
        #pragma unroll
        for (int r = 0; r < 7; ++r)
            rs[r] = (v[r].x + v[r].y) + (v[r].z + v[r].w);
        #pragma unroll
        for (int off = 16; off; off >>= 1) {
            #pragma unroll
            for (int r = 0; r < 7; ++r)
                rs[r] += __shfl_down_sync(0xffffffffu, rs[r], off);
        }
        if (lane == 0) {
            #pragma unroll
            for (int r = 0; r < 7; ++r)
                outp[base + half * 7 + r] = rs[r] * (1.f / (float)W);
        }
        #pragma unroll
        for (int r = 0; r < 7; ++r) {
            c0 += v[r].x; c1 += v[r].y; c2 += v[r].z; c3 += v[r].w;
        }
    }

    if (act) {
        scol[warp][lane * 4 + 0] = c0;
        scol[warp][lane * 4 + 1] = c1;
        scol[warp][lane * 4 + 2] = c2;
        scol[warp][lane * 4 + 3] = c3;
    }
    __syncthreads();
    if (tid < 112) {
        float t = 0.f;
        #pragma unroll
        for (int w8 = 0; w8 < 8; ++w8) t += scol[w8][tid];
        outp[112 + tid] = t * (1.f / (float)H);
    }
}

// ---------------------------------------------------------------------------
// Kernel 2: per-(n,pos) block (1792 blocks, 256 threads): BN -> ds (C->8) ->
// ReLU -> us (8->C) -> sigmoid. Writes attention g_att[n][c][pos].
// ---------------------------------------------------------------------------
__global__ void att_kernel(const float* __restrict__ g1, const float* __restrict__ b1,
                           const float* __restrict__ m1, const float* __restrict__ v1,
                           const float* __restrict__ g2, const float* __restrict__ b2,
                           const float* __restrict__ m2, const float* __restrict__ v2,
                           const float* __restrict__ dsw, const float* __restrict__ dsb,
                           const float* __restrict__ usw, const float* __restrict__ usb) {
    const int b   = blockIdx.x;        // n*L + pos
    const int n   = b / L;
    const int pos = b % L;
    const int c   = threadIdx.x;       // 256

    float val = g_pool[((size_t)n * C + c) * L + pos];

    float sc, tb;
    if (pos < H) {
        float s = g1[c] * rsqrtf(v1[c] + 1e-5f);
        sc = s; tb = b1[c] - m1[c] * s;
    } else {
        float s = g2[c] * rsqrtf(v2[c] + 1e-5f);
        sc = s; tb = b2[c] - m2[c] * s;
    }
    val = fmaf(val, sc, tb);

    // down-projection partials: p[m] = dsw[m][c] * val
    float p[8];
    #pragma unroll
    for (int m = 0; m < 8; ++m) p[m] = dsw[m * C + c] * val;

    #pragma unroll
    for (int off = 16; off; off >>= 1) {
        #pragma unroll
        for (int m = 0; m < 8; ++m)
            p[m] += __shfl_down_sync(0xffffffffu, p[m], off);
    }

    __shared__ float wp[8][8];   // [warp][m]
    __shared__ float dv[8];
    const int warp = c >> 5, lane = c & 31;
    if (lane == 0) {
        #pragma unroll
        for (int m = 0; m < 8; ++m) wp[warp][m] = p[m];
    }
    __syncthreads();
    if (c < 8) {
        float s = dsb[c];
        #pragma unroll
        for (int w8 = 0; w8 < 8; ++w8) s += wp[w8][c];
        dv[c] = fmaxf(s, 0.f);       // ReLU
    }
    __syncthreads();

    float u = usb[c];
    #pragma unroll
    for (int m = 0; m < 8; ++m) u = fmaf(usw[c * 8 + m], dv[m], u);

    float a = 1.f / (1.f + expf(-u));  // sigmoid
    g_att[((size_t)n * C + c) * L + pos] = a;
}

// ---------------------------------------------------------------------------
// Kernel 3: out = hswish(x * a_w * a_h + x).
// REVERSED block order: pool cached planes 0->2047, so plane 2047 is MRU.
// Reading MRU-first means the write stream's LRU evictions never front-run
// our reads -> x stays L2-resident. Non-allocating (__stwt) stores keep the
// output stream out of L2 entirely. Each block owns 1024 contiguous float4.
// ---------------------------------------------------------------------------
__device__ __forceinline__ float hsw(float v, float aw, float ah) {
    float t = fmaf(v * aw, ah, v);                       // v*aw*ah + v
    return t * __saturatef((t + 3.f) * (1.f / 6.f));     // t * clip(t+3,0,6)/6
}

__global__ void apply_kernel(const float4* __restrict__ x, float4* __restrict__ out) {
    const int rbid = gridDim.x - 1 - blockIdx.x;          // reverse traversal
    const int base = rbid * 1024 + threadIdx.x;
    #pragma unroll
    for (int k = 0; k < 4; ++k) {
        const int idx   = base + k * 256;
        const int w4    = idx % 28;
        const int rest  = idx / 28;
        const int h     = rest % H;
        const int plane = rest / H;                       // n*C + c

        const float  ah = __ldg(&g_att[(size_t)plane * L + h]);
        const float4 aw = __ldg((const float4*)&g_att[(size_t)plane * L + H + w4 * 4]);
        float4 v = __ldg(&x[idx]);

        float4 r;
        r.x = hsw(v.x, aw.x, ah);
        r.y = hsw(v.y, aw.y, ah);
        r.z = hsw(v.z, aw.z, ah);
        r.w = hsw(v.w, aw.w, ah);
        __stwt(&out[idx], r);     // write-through: don't allocate in L2
    }
}

// ---------------------------------------------------------------------------
extern "C" void kernel_launch(void* const* d_in, const int* in_sizes, int n_in,
                              void* d_out, int out_size) {
    const float* x   = (const float*)d_in[0];
    const float* g1  = (const float*)d_in[1];
    const float* b1  = (const float*)d_in[2];
    const float* m1  = (const float*)d_in[3];
    const float* v1  = (const float*)d_in[4];
    const float* g2  = (const float*)d_in[5];
    const float* b2  = (const float*)d_in[6];
    const float* m2  = (const float*)d_in[7];
    const float* v2  = (const float*)d_in[8];
    const float* dsw = (const float*)d_in[9];
    const float* dsb = (const float*)d_in[10];
    const float* usw = (const float*)d_in[11];
    const float* usb = (const float*)d_in[12];
    float* out = (float*)d_out;

    pool_kernel<<<PLANES, 256>>>(x);
    att_kernel<<<NB * L, C>>>(g1, b1, m1, v1, g2, b2, m2, v2, dsw, dsb, usw, usb);
    apply_kernel<<<TOTAL4 / 1024, 256>>>((const float4*)x, (float4*)out);
}